// round 15
// baseline (speedup 1.0000x reference)
#include <cuda_runtime.h>
#include <cuda_fp16.h>
#include <mma.h>

#define EH    256
#define RH    128
#define RREL  500
#define NSEG  (RREL*4)
#define N_MAX 50000
#define E_MAX 800000
#define NB    592          // kT grid = 148 SMs x 4 CTAs (guaranteed co-resident)
#define ECHUNK 1352        // edges per CTA chunk (NB*ECHUNK >= E, mult of 4)
#define SPLIT 8            // gather work items per relation
#define GROWS 64           // kG rows per CTA
#define FSTR  400          // kG fragment stride in halves (800B)
#define FLD   24           // kG fragment leading dim (halves)

// ---------------- device scratch (static; no allocations) ----------------
__device__ float4 g_Ssrc[N_MAX];           // per-node (s_hh0, s_hh1, s_th0, s_th1)
__device__ float4 g_Sdst[N_MAX];           // per-node (s_tt0, s_tt1, s_ht0, s_ht1)
__device__ __half g_xrh[(size_t)N_MAX*RH]; // fp16 x_e @ w_h^T
__device__ __half g_xrt[(size_t)N_MAX*RH]; // fp16 x_e @ w_t^T
__device__ __align__(512) __half g_whf[RH*EH];  // w_h fragment-contiguous
__device__ __align__(512) __half g_wtf[RH*EH];  // w_t fragment-contiguous
__device__ float  g_U[8*EH];               // fused score vectors
__device__ float  g_sum[NSEG];             // written by kT phase 2
__device__ int    g_cnt[RREL];             // per-rel totals (written by kS)
__device__ int    g_start[RREL+1];
__device__ int    g_done;                  // kS last-block counter (self-resetting)
__device__ int    g_bcnt[NB*RREL];         // per-block rel histogram    [b][r]
__device__ int    g_boff[NB*RREL];         // per-block LOCAL prefix     [b][r]
__device__ float4 g_sM[E_MAX];             // sorted: (src, dst, h2(ex0,ex1), h2(ex2,ex3))
// persistent-kernel grid barrier state (generation-based; survives replays)
__device__ volatile unsigned g_gen;
__device__ unsigned g_barcnt;

__device__ __forceinline__ float lrelu(float x){ return x > 0.f ? x : 0.01f*x; }

__device__ __forceinline__ float h2_as_f(__half2 h){
    return __uint_as_float(*reinterpret_cast<unsigned*>(&h));
}
__device__ __forceinline__ __half2 f_as_h2(float f){
    unsigned u = __float_as_uint(f);
    return *reinterpret_cast<__half2*>(&u);
}

// grid-wide spin barrier: safe because kT's 592 CTAs (4/SM x 148) are all
// resident (launch_bounds(256,4) caps regs at 64) and the GPU is otherwise idle.
__device__ __forceinline__ void grid_bar(){
    __syncthreads();
    if (threadIdx.x == 0){
        __threadfence();
        unsigned gen = g_gen;
        if (atomicAdd(&g_barcnt, 1u) == (unsigned)gridDim.x - 1u){
            g_barcnt = 0u;
            __threadfence();
            g_gen = gen + 1u;
        } else {
            while (g_gen == gen) { }
        }
    }
    __syncthreads();
}

// ---------------- kernel A: fused score vectors U (one block per vector) ----------------
__global__ void kA(const float* __restrict__ w_h, const float* __restrict__ w_t,
                   const float* __restrict__ a_h, const float* __restrict__ a_t){
    __shared__ float sa[RH];
    int j = blockIdx.x;   // 0..7
    const float* av = (j < 4) ? a_h : a_t;
    int arow = ((j & 1) ? 1 : 0);
    const float* wm = (j == 0 || j == 1 || j == 6 || j == 7) ? w_h : w_t;
    for (int i = threadIdx.x; i < RH; i += blockDim.x) sa[i] = av[arow*RH + i];
    __syncthreads();
    int c = threadIdx.x;   // 256 threads == EH
    float u0 = 0.f, u1 = 0.f, u2 = 0.f, u3 = 0.f;
    #pragma unroll 4
    for (int k = 0; k < RH; k += 4){
        u0 = fmaf(sa[k+0], __ldg(&wm[(k+0)*EH + c]), u0);
        u1 = fmaf(sa[k+1], __ldg(&wm[(k+1)*EH + c]), u1);
        u2 = fmaf(sa[k+2], __ldg(&wm[(k+2)*EH + c]), u2);
        u3 = fmaf(sa[k+3], __ldg(&wm[(k+3)*EH + c]), u3);
    }
    g_U[j*EH + c] = (u0 + u1) + (u2 + u3);
}

// ------- kernel W: weights -> fragment-contiguous fp16 layout + zero out -------
__global__ void kW(const float* __restrict__ w_h, const float* __restrict__ w_t,
                   float* __restrict__ out){
    int tid = blockIdx.x*blockDim.x + threadIdx.x;
    int stride = gridDim.x*blockDim.x;
    for (int t = tid; t < RH*EH; t += stride){
        int kin = t & 15;
        int n   = (t >> 4) & 15;
        int blk = t >> 8;
        int kb  = blk & 15;          // EH/16 = 16
        int ct  = blk >> 4;          // RH/16 = 8
        int src = (ct*16 + n)*EH + kb*16 + kin;
        g_whf[t] = __float2half_rn(__ldg(&w_h[src]));
        g_wtf[t] = __float2half_rn(__ldg(&w_t[src]));
    }
    for (int i = tid; i < RREL*RH; i += stride) out[i] = 0.f;
}

// ---------- kernel H: int4 per-block rel histogram (looped chunks) ----------
__global__ void __launch_bounds__(256) kH(const int* __restrict__ rel, int E){
    __shared__ int scnt[RREL];
    int b = blockIdx.x;
    for (int i = threadIdx.x; i < RREL; i += blockDim.x) scnt[i] = 0;
    __syncthreads();
    int e0 = b*ECHUNK, e1 = min(E, e0 + ECHUNK);
    for (int eb = e0 + threadIdx.x*4; eb < e1; eb += 256*4){
        if (eb + 4 <= e1){
            int4 v = *(const int4*)&rel[eb];
            atomicAdd(&scnt[v.x], 1); atomicAdd(&scnt[v.y], 1);
            atomicAdd(&scnt[v.z], 1); atomicAdd(&scnt[v.w], 1);
        } else {
            for (int e = eb; e < e1; e++) atomicAdd(&scnt[rel[e]], 1);
        }
    }
    __syncthreads();
    for (int i = threadIdx.x; i < RREL; i += blockDim.x)
        g_bcnt[b*RREL + i] = scnt[i];
}

// ------ kernel G: tensor-core projection, double-buffered, one matrix per blockIdx.y ------
__global__ void __launch_bounds__(256) kG(const float* __restrict__ x_e, int N){
    using namespace nvcuda;
    __shared__ __align__(1024) __half Asm[2][16*FSTR]; // 2 x 12.8KB padded fragments
    __shared__ float Csm[32*128];                      // 16KB epilogue staging
    int tid  = threadIdx.x;
    int warp = tid >> 5;                  // 0..7 -> col tile warp*16
    int row0 = blockIdx.x * GROWS;
    const __half* Bfrag = blockIdx.y ? g_wtf : g_whf;
    __half*       dstg  = blockIdx.y ? g_xrt : g_xrh;

    int rr[4], rtq[4], kkq[4], kinq[4];
    #pragma unroll
    for (int q = 0; q < 4; q++){
        int i = tid + 256*q;
        int r = i >> 4, c4 = i & 15;
        rr[q]   = r;
        rtq[q]  = r >> 4;
        kkq[q]  = c4 >> 2;
        kinq[q] = (c4 & 3) * 4;
    }

    wmma::fragment<wmma::accumulator,16,16,16,float> acc[4];
    #pragma unroll
    for (int rt = 0; rt < 4; rt++) wmma::fill_fragment(acc[rt], 0.f);

    float4 v[4];
    #pragma unroll
    for (int q = 0; q < 4; q++){
        int gr = row0 + rr[q];
        v[q] = make_float4(0.f,0.f,0.f,0.f);
        if (gr < N) v[q] = __ldg((const float4*)(x_e + (size_t)gr*EH) + (tid + 256*q & 15));
    }
    #pragma unroll
    for (int q = 0; q < 4; q++){
        __half* base = &Asm[0][(rtq[q]*4 + kkq[q])*FSTR + (rr[q] & 15)*FLD + kinq[q]];
        ((__half2*)base)[0] = __floats2half2_rn(v[q].x, v[q].y);
        ((__half2*)base)[1] = __floats2half2_rn(v[q].z, v[q].w);
    }
    __syncthreads();

    #pragma unroll
    for (int t = 0; t < 4; t++){
        int cb = t & 1, nb = (t + 1) & 1;
        int k0n = (t + 1) * 64;
        float4 vn[4];
        if (t < 3){
            #pragma unroll
            for (int q = 0; q < 4; q++){
                int gr = row0 + rr[q];
                vn[q] = make_float4(0.f,0.f,0.f,0.f);
                if (gr < N) vn[q] = __ldg((const float4*)(x_e + (size_t)gr*EH + k0n) + (tid + 256*q & 15));
            }
        }
        #pragma unroll
        for (int kk = 0; kk < 4; kk++){
            wmma::fragment<wmma::matrix_b,16,16,16,__half,wmma::col_major> b;
            wmma::load_matrix_sync(b, Bfrag + (size_t)(warp*16 + t*4 + kk)*256, 16);
            #pragma unroll
            for (int rt = 0; rt < 4; rt++){
                wmma::fragment<wmma::matrix_a,16,16,16,__half,wmma::row_major> a;
                wmma::load_matrix_sync(a, &Asm[cb][(rt*4 + kk)*FSTR], FLD);
                wmma::mma_sync(acc[rt], a, b, acc[rt]);
            }
        }
        if (t < 3){
            #pragma unroll
            for (int q = 0; q < 4; q++){
                __half* base = &Asm[nb][(rtq[q]*4 + kkq[q])*FSTR + (rr[q] & 15)*FLD + kinq[q]];
                ((__half2*)base)[0] = __floats2half2_rn(vn[q].x, vn[q].y);
                ((__half2*)base)[1] = __floats2half2_rn(vn[q].z, vn[q].w);
            }
            __syncthreads();
        }
    }
    #pragma unroll
    for (int chunk = 0; chunk < 2; chunk++){
        __syncthreads();
        #pragma unroll
        for (int rtl = 0; rtl < 2; rtl++)
            wmma::store_matrix_sync(&Csm[rtl*16*RH + warp*16], acc[chunk*2 + rtl],
                                    RH, wmma::mem_row_major);
        __syncthreads();
        for (int i = tid; i < 32*64; i += 256){
            int r = i >> 6, c2 = i & 63;
            int gr = row0 + chunk*32 + r;
            if (gr < N)
                ((__half2*)(dstg + (size_t)gr*RH))[c2] =
                    __floats2half2_rn(Csm[r*RH + 2*c2], Csm[r*RH + 2*c2 + 1]);
        }
    }
}

// ---------------- kernel B: per-node scores (fp32 exact) ----------------
__global__ void kB(const float* __restrict__ x_e, int N){
    __shared__ float sU[8*EH];
    for (int i = threadIdx.x; i < 8*EH; i += blockDim.x) sU[i] = g_U[i];
    __syncthreads();
    int warp = threadIdx.x >> 5, lane = threadIdx.x & 31;
    int n = blockIdx.x*8 + warp;
    if (n >= N) return;
    const float4* row = (const float4*)(x_e + (size_t)n*EH);
    float4 v0 = __ldg(&row[lane]);
    float4 v1 = __ldg(&row[lane+32]);
    float p[8];
    #pragma unroll
    for (int j = 0; j < 8; j++){
        const float* U = &sU[j*EH];
        float s;
        s  = v0.x*U[lane*4+0] + v0.y*U[lane*4+1] + v0.z*U[lane*4+2] + v0.w*U[lane*4+3];
        s += v1.x*U[128+lane*4+0] + v1.y*U[128+lane*4+1]
           + v1.z*U[128+lane*4+2] + v1.w*U[128+lane*4+3];
        p[j] = s;
    }
    #pragma unroll
    for (int j = 0; j < 8; j++){
        #pragma unroll
        for (int o = 16; o > 0; o >>= 1) p[j] += __shfl_xor_sync(0xffffffffu, p[j], o);
    }
    if (lane == 0){
        g_Ssrc[n] = make_float4(p[0], p[1], p[2], p[3]);
        g_Sdst[n] = make_float4(p[4], p[5], p[6], p[7]);
    }
}

// ---- kernel S: per-rel scan across blocks -> prefixes + totals; last block scans totals ----
__global__ void __launch_bounds__(896) kS(){
    __shared__ int wsum[32];
    __shared__ int last;
    int r = blockIdx.x;
    int t = threadIdx.x, lane = t & 31, warp = t >> 5;   // 28 warps
    int v = (t < NB) ? g_bcnt[t*RREL + r] : 0;
    int incl = v;
    #pragma unroll
    for (int o = 1; o < 32; o <<= 1){
        int x = __shfl_up_sync(0xffffffffu, incl, o);
        if (lane >= o) incl += x;
    }
    if (lane == 31) wsum[warp] = incl;
    __syncthreads();
    if (warp == 0){
        int w = (lane < 28) ? wsum[lane] : 0;
        int wi = w;
        #pragma unroll
        for (int o = 1; o < 32; o <<= 1){
            int x = __shfl_up_sync(0xffffffffu, wi, o);
            if (lane >= o) wi += x;
        }
        wsum[lane] = wi - w;   // exclusive warp prefix
    }
    __syncthreads();
    int pos = wsum[warp] + incl;
    if (t < NB)      g_boff[t*RREL + r] = pos - v;
    if (t == NB - 1) g_cnt[r] = pos;
    __threadfence();
    if (t == 0) last = (atomicAdd(&g_done, 1) == (int)gridDim.x - 1);
    __syncthreads();
    if (last){
        __threadfence();
        if (t < 32){
            int carry = 0;
            for (int base = 0; base < RREL; base += 32){
                int idx  = base + t;
                int orig = (idx < RREL) ? g_cnt[idx] : 0;
                int vv = orig;
                #pragma unroll
                for (int o = 1; o < 32; o <<= 1){
                    int x = __shfl_up_sync(0xffffffffu, vv, o);
                    if (t >= o) vv += x;
                }
                if (idx < RREL) g_start[idx] = carry + vv - orig;
                carry += __shfl_sync(0xffffffffu, vv, 31);
            }
            if (t == 0){ g_start[RREL] = carry; g_done = 0; }  // reset for next replay
        }
    }
}

// ==== kernel T: fused tail = scatter -> bar -> sums -> bar -> gather ====
__global__ void __launch_bounds__(256, 4) kT(const int* __restrict__ ei,
                                             const int* __restrict__ rel, int E,
                                             float* __restrict__ out){
    __shared__ int    scur[RREL];
    __shared__ float  redv[8][4];
    __shared__ float4 redS[8][32];
    __shared__ float4 redD[8][32];
    int b = blockIdx.x;
    int tid = threadIdx.x;
    int warp = tid >> 5, lane = tid & 31;

    // ---------- phase 1: exp + counting-sort scatter ----------
    for (int i = tid; i < RREL; i += 256)
        scur[i] = g_start[i] + g_boff[b*RREL + i];
    __syncthreads();
    {
        int e0 = b*ECHUNK, e1 = min(E, e0 + ECHUNK);
        for (int eb = e0 + tid*4; eb < e1; eb += 256*4){
            int nv = min(4, e1 - eb);
            int s[4], d[4], rr[4];
            if (nv == 4){
                int4 vs = *(const int4*)&ei[eb];
                int4 vd = *(const int4*)&ei[E + eb];
                int4 vr = *(const int4*)&rel[eb];
                s[0]=vs.x; s[1]=vs.y; s[2]=vs.z; s[3]=vs.w;
                d[0]=vd.x; d[1]=vd.y; d[2]=vd.z; d[3]=vd.w;
                rr[0]=vr.x; rr[1]=vr.y; rr[2]=vr.z; rr[3]=vr.w;
            } else {
                for (int i = 0; i < nv; i++){
                    s[i]  = ei[eb+i];
                    d[i]  = ei[E+eb+i];
                    rr[i] = rel[eb+i];
                }
            }
            float4 fs[4], fd[4];
            #pragma unroll
            for (int i = 0; i < 4; i++) if (i < nv){
                fs[i] = __ldg(&g_Ssrc[s[i]]);
                fd[i] = __ldg(&g_Sdst[d[i]]);
            }
            #pragma unroll
            for (int i = 0; i < 4; i++) if (i < nv){
                int r = rr[i];
                // scores ~ N(0,2): exp without max-shift is safe in fp32
                float x0 = __expf(lrelu(fs[i].x + fd[i].x));
                float x1 = __expf(lrelu(fs[i].y + fd[i].y));
                float x2 = __expf(lrelu(fs[i].z + fd[i].z));
                float x3 = __expf(lrelu(fs[i].w + fd[i].w));
                int pos = atomicAdd(&scur[r], 1);
                g_sM[pos] = make_float4(__int_as_float(s[i]), __int_as_float(d[i]),
                                        h2_as_f(__floats2half2_rn(x0, x1)),
                                        h2_as_f(__floats2half2_rn(x2, x3)));
            }
        }
    }
    grid_bar();

    // ---------- phase 2: per-rel softmax sums (CTA r handles rel r) ----------
    if (b < RREL){
        int beg = g_start[b], end = g_start[b+1];
        float s0=0.f, s1=0.f, s2=0.f, s3=0.f;
        for (int i = beg + tid; i < end; i += 256){
            float4 m = __ldg(&g_sM[i]);
            float2 e01 = __half22float2(f_as_h2(m.z));
            float2 e23 = __half22float2(f_as_h2(m.w));
            s0 += e01.x; s1 += e01.y; s2 += e23.x; s3 += e23.y;
        }
        #pragma unroll
        for (int o = 16; o > 0; o >>= 1){
            s0 += __shfl_xor_sync(0xffffffffu, s0, o);
            s1 += __shfl_xor_sync(0xffffffffu, s1, o);
            s2 += __shfl_xor_sync(0xffffffffu, s2, o);
            s3 += __shfl_xor_sync(0xffffffffu, s3, o);
        }
        if (lane == 0){ redv[warp][0]=s0; redv[warp][1]=s1; redv[warp][2]=s2; redv[warp][3]=s3; }
        __syncthreads();
        if (tid < 4){
            float t = 0.f;
            #pragma unroll
            for (int w = 0; w < 8; w++) t += redv[w][tid];
            g_sum[4*b + tid] = t;
        }
    }
    grid_bar();

    // ---------- phase 3: gather-accumulate over (rel, part) work items ----------
    for (int item = b; item < RREL*SPLIT; item += NB){
        int r    = item / SPLIT;
        int part = item % SPLIT;
        int beg = g_start[r], end = g_start[r+1], n = end - beg;
        int p0 = beg + (int)(((long long)n *  part     ) / SPLIT);
        int p1 = beg + (int)(((long long)n * (part + 1)) / SPLIT);
        float inv0 = 1.f/(g_sum[4*r+0] + 1e-16f);
        float inv1 = 1.f/(g_sum[4*r+1] + 1e-16f);
        float inv2 = 1.f/(g_sum[4*r+2] + 1e-16f);
        float inv3 = 1.f/(g_sum[4*r+3] + 1e-16f);

        float4 aS = make_float4(0.f,0.f,0.f,0.f);
        float4 aD = make_float4(0.f,0.f,0.f,0.f);

        int i = p0 + warp;
        float4 m0 = make_float4(0.f,0.f,0.f,0.f);
        uint2 hs0 = make_uint2(0u,0u), ht0 = make_uint2(0u,0u);
        if (i < p1){
            m0 = __ldg(&g_sM[i]);
            int s = __float_as_int(m0.x), d = __float_as_int(m0.y);
            hs0 = __ldg((const uint2*)(g_xrh + (size_t)s*RH) + lane);
            ht0 = __ldg((const uint2*)(g_xrt + (size_t)d*RH) + lane);
        }
        while (i < p1){
            int j = i + 8;
            float4 m1 = make_float4(0.f,0.f,0.f,0.f);
            uint2 hs1 = make_uint2(0u,0u), ht1 = make_uint2(0u,0u);
            if (j < p1){
                m1 = __ldg(&g_sM[j]);
                int s = __float_as_int(m1.x), d = __float_as_int(m1.y);
                hs1 = __ldg((const uint2*)(g_xrh + (size_t)s*RH) + lane);
                ht1 = __ldg((const uint2*)(g_xrt + (size_t)d*RH) + lane);
            }
            {
                float2 e01 = __half22float2(f_as_h2(m0.z));
                float2 e23 = __half22float2(f_as_h2(m0.w));
                float w1 = e01.x*inv0 + e01.y*inv1;
                float w2 = e23.x*inv2 + e23.y*inv3;
                float2 f;
                f = __half22float2(*reinterpret_cast<__half2*>(&hs0.x));
                aS.x = fmaf(w1, f.x, aS.x); aS.y = fmaf(w1, f.y, aS.y);
                f = __half22float2(*reinterpret_cast<__half2*>(&hs0.y));
                aS.z = fmaf(w1, f.x, aS.z); aS.w = fmaf(w1, f.y, aS.w);
                f = __half22float2(*reinterpret_cast<__half2*>(&ht0.x));
                aD.x = fmaf(w2, f.x, aD.x); aD.y = fmaf(w2, f.y, aD.y);
                f = __half22float2(*reinterpret_cast<__half2*>(&ht0.y));
                aD.z = fmaf(w2, f.x, aD.z); aD.w = fmaf(w2, f.y, aD.w);
            }
            m0 = m1; hs0 = hs1; ht0 = ht1; i = j;
        }

        redS[warp][lane] = aS;
        redD[warp][lane] = aD;
        __syncthreads();

        if (tid < 32){
            float4 s = make_float4(0.f,0.f,0.f,0.f);
            float4 dd = make_float4(0.f,0.f,0.f,0.f);
            #pragma unroll
            for (int w = 0; w < 8; w++){
                float4 vs = redS[w][tid], vd = redD[w][tid];
                s.x += vs.x; s.y += vs.y; s.z += vs.z; s.w += vs.w;
                dd.x += vd.x; dd.y += vd.y; dd.z += vd.z; dd.w += vd.w;
            }
            float* o = &out[r*RH + 4*tid];
            atomicAdd(o+0, 0.25f*(s.x + dd.x));
            atomicAdd(o+1, 0.25f*(s.y + dd.y));
            atomicAdd(o+2, 0.25f*(s.z + dd.z));
            atomicAdd(o+3, 0.25f*(s.w + dd.w));
        }
        __syncthreads();   // smem reuse across items
    }
}

// ---------------- streams/events (host-side objects, created at load time) ----------------
struct HXStreams {
    cudaStream_t sB, sC;
    cudaEvent_t  evRoot, evB, evC;
    HXStreams(){
        cudaStreamCreateWithFlags(&sB, cudaStreamNonBlocking);
        cudaStreamCreateWithFlags(&sC, cudaStreamNonBlocking);
        cudaEventCreateWithFlags(&evRoot, cudaEventDisableTiming);
        cudaEventCreateWithFlags(&evB,    cudaEventDisableTiming);
        cudaEventCreateWithFlags(&evC,    cudaEventDisableTiming);
    }
};
static HXStreams hx;

// ---------------- launcher: fork 3 chains, single fused tail ----------------
extern "C" void kernel_launch(void* const* d_in, const int* in_sizes, int n_in,
                              void* d_out, int out_size){
    const float* x_e = (const float*)d_in[0];
    const int*   ei  = (const int*)  d_in[1];
    const int*   rel = (const int*)  d_in[2];
    const float* w_h = (const float*)d_in[3];
    const float* w_t = (const float*)d_in[4];
    const float* a_h = (const float*)d_in[5];
    const float* a_t = (const float*)d_in[6];
    float* out = (float*)d_out;

    int N = in_sizes[0] / EH;
    int E = in_sizes[2];

    // fork immediately
    cudaEventRecord(hx.evRoot, 0);
    cudaStreamWaitEvent(hx.sB, hx.evRoot, 0);
    cudaStreamWaitEvent(hx.sC, hx.evRoot, 0);

    // chain 1 (main): U vectors -> scores
    kA<<<8, 256>>>(w_h, w_t, a_h, a_t);
    kB<<<(N + 7)/8, 256>>>(x_e, N);

    // chain 2 (stream B): fp16 weights -> tensor-core value projection
    kW<<<128, 256, 0, hx.sB>>>(w_h, w_t, out);
    dim3 ggrid((N + GROWS - 1)/GROWS, 2);
    kG<<<ggrid, 256, 0, hx.sB>>>(x_e, N);
    cudaEventRecord(hx.evB, hx.sB);

    // chain 3 (stream C): histogram -> prefix structure
    kH<<<NB, 256, 0, hx.sC>>>(rel, E);
    kS<<<RREL, 896, 0, hx.sC>>>();
    cudaEventRecord(hx.evC, hx.sC);

    // join all chains -> fused tail (GPU otherwise idle => all 592 CTAs resident)
    cudaStreamWaitEvent(0, hx.evC, 0);
    cudaStreamWaitEvent(0, hx.evB, 0);
    kT<<<NB, 256>>>(ei, rel, E, out);
}

// round 16
// speedup vs baseline: 1.2403x; 1.2403x over previous
#include <cuda_runtime.h>
#include <cuda_fp16.h>
#include <mma.h>

#define EH    256
#define RH    128
#define RREL  500
#define NSEG  (RREL*4)
#define N_MAX 50000
#define E_MAX 800000
#define NB    888          // kE / kH block count
#define ECHUNK 904         // edges per block (NB*ECHUNK >= E, mult of 4)
#define SPLIT 8            // kF blocks per relation
#define GROWS 64           // kG rows per CTA
#define FSTR  400          // kG fragment stride in halves (800B)
#define FLD   24           // kG fragment leading dim (halves)

// ---------------- device scratch (static; no allocations) ----------------
__device__ float4 g_Ssrc[N_MAX];           // per-node (s_hh0, s_hh1, s_th0, s_th1)
__device__ float4 g_Sdst[N_MAX];           // per-node (s_tt0, s_tt1, s_ht0, s_ht1)
__device__ __half g_xrh[(size_t)N_MAX*RH]; // fp16 x_e @ w_h^T
__device__ __half g_xrt[(size_t)N_MAX*RH]; // fp16 x_e @ w_t^T
__device__ __align__(512) __half g_whf[RH*EH];  // w_h fragment-contiguous
__device__ __align__(512) __half g_wtf[RH*EH];  // w_t fragment-contiguous
__device__ float  g_U[8*EH];               // fused score vectors
__device__ float  g_sum[NSEG];             // written by kSum (no atomics)
__device__ int    g_cnt[RREL];             // per-rel totals (written by kS)
__device__ int    g_start[RREL+1];
__device__ int    g_done;                  // kS last-block counter (self-resetting)
__device__ int    g_bcnt[NB*RREL];         // per-block rel histogram    [b][r]
__device__ int    g_boff[NB*RREL];         // per-block LOCAL prefix     [b][r]
__device__ float4 g_sM[E_MAX];             // sorted: (src, dst, h2(ex0,ex1), h2(ex2,ex3))

__device__ __forceinline__ float lrelu(float x){ return x > 0.f ? x : 0.01f*x; }

__device__ __forceinline__ float h2_as_f(__half2 h){
    return __uint_as_float(*reinterpret_cast<unsigned*>(&h));
}
__device__ __forceinline__ __half2 f_as_h2(float f){
    unsigned u = __float_as_uint(f);
    return *reinterpret_cast<__half2*>(&u);
}

// ---- kernel P: fused prep = U vectors (blocks 0..7) + fp16 weights/zero out (8..135) ----
__global__ void __launch_bounds__(256) kP(const float* __restrict__ w_h,
                                          const float* __restrict__ w_t,
                                          const float* __restrict__ a_h,
                                          const float* __restrict__ a_t,
                                          float* __restrict__ out){
    int bb = blockIdx.x;
    if (bb < 8){
        __shared__ float sa[RH];
        int j = bb;   // 0..7
        const float* av = (j < 4) ? a_h : a_t;
        int arow = ((j & 1) ? 1 : 0);
        const float* wm = (j == 0 || j == 1 || j == 6 || j == 7) ? w_h : w_t;
        for (int i = threadIdx.x; i < RH; i += blockDim.x) sa[i] = av[arow*RH + i];
        __syncthreads();
        int c = threadIdx.x;   // 256 threads == EH
        float u0 = 0.f, u1 = 0.f, u2 = 0.f, u3 = 0.f;
        #pragma unroll 4
        for (int k = 0; k < RH; k += 4){
            u0 = fmaf(sa[k+0], __ldg(&w_h[(k+0)*EH + c]) * 0.f + __ldg(&wm[(k+0)*EH + c]), u0);
            u1 = fmaf(sa[k+1], __ldg(&wm[(k+1)*EH + c]), u1);
            u2 = fmaf(sa[k+2], __ldg(&wm[(k+2)*EH + c]), u2);
            u3 = fmaf(sa[k+3], __ldg(&wm[(k+3)*EH + c]), u3);
        }
        g_U[j*EH + c] = (u0 + u1) + (u2 + u3);
    } else {
        int tid = (bb - 8)*256 + threadIdx.x;
        int stride = 128*256;
        for (int t = tid; t < RH*EH; t += stride){
            int kin = t & 15;
            int n   = (t >> 4) & 15;
            int blk = t >> 8;
            int kb  = blk & 15;          // EH/16 = 16
            int ct  = blk >> 4;          // RH/16 = 8
            int src = (ct*16 + n)*EH + kb*16 + kin;
            g_whf[t] = __float2half_rn(__ldg(&w_h[src]));
            g_wtf[t] = __float2half_rn(__ldg(&w_t[src]));
        }
        for (int i = tid; i < RREL*RH; i += stride) out[i] = 0.f;
    }
}

// ---------- kernel H: int4 per-block rel histogram ----------
__global__ void __launch_bounds__(256) kH(const int* __restrict__ rel, int E){
    __shared__ int scnt[RREL];
    int b = blockIdx.x;
    for (int i = threadIdx.x; i < RREL; i += blockDim.x) scnt[i] = 0;
    __syncthreads();
    int e0 = b*ECHUNK, e1 = min(E, e0 + ECHUNK);
    int eb = e0 + threadIdx.x*4;
    if (eb < e1){
        if (eb + 4 <= e1){
            int4 v = *(const int4*)&rel[eb];
            atomicAdd(&scnt[v.x], 1); atomicAdd(&scnt[v.y], 1);
            atomicAdd(&scnt[v.z], 1); atomicAdd(&scnt[v.w], 1);
        } else {
            for (int e = eb; e < e1; e++) atomicAdd(&scnt[rel[e]], 1);
        }
    }
    __syncthreads();
    for (int i = threadIdx.x; i < RREL; i += blockDim.x)
        g_bcnt[b*RREL + i] = scnt[i];
}

// ------ kernel G: tensor-core projection, double-buffered, one matrix per blockIdx.y ------
// launch_bounds(256,4): occupancy experiment — cap regs at 64 for 4 CTAs/SM.
__global__ void __launch_bounds__(256, 4) kG(const float* __restrict__ x_e, int N){
    using namespace nvcuda;
    __shared__ __align__(1024) __half Asm[2][16*FSTR]; // 2 x 12.8KB padded fragments
    __shared__ float Csm[32*128];                      // 16KB epilogue staging
    int tid  = threadIdx.x;
    int warp = tid >> 5;                  // 0..7 -> col tile warp*16
    int row0 = blockIdx.x * GROWS;
    const __half* Bfrag = blockIdx.y ? g_wtf : g_whf;
    __half*       dstg  = blockIdx.y ? g_xrt : g_xrh;

    int rr[4], rtq[4], kkq[4], kinq[4];
    #pragma unroll
    for (int q = 0; q < 4; q++){
        int i = tid + 256*q;
        int r = i >> 4, c4 = i & 15;
        rr[q]   = r;
        rtq[q]  = r >> 4;
        kkq[q]  = c4 >> 2;
        kinq[q] = (c4 & 3) * 4;
    }

    wmma::fragment<wmma::accumulator,16,16,16,float> acc[4];
    #pragma unroll
    for (int rt = 0; rt < 4; rt++) wmma::fill_fragment(acc[rt], 0.f);

    float4 v[4];
    #pragma unroll
    for (int q = 0; q < 4; q++){
        int gr = row0 + rr[q];
        v[q] = make_float4(0.f,0.f,0.f,0.f);
        if (gr < N) v[q] = __ldg((const float4*)(x_e + (size_t)gr*EH) + (tid + 256*q & 15));
    }
    #pragma unroll
    for (int q = 0; q < 4; q++){
        __half* base = &Asm[0][(rtq[q]*4 + kkq[q])*FSTR + (rr[q] & 15)*FLD + kinq[q]];
        ((__half2*)base)[0] = __floats2half2_rn(v[q].x, v[q].y);
        ((__half2*)base)[1] = __floats2half2_rn(v[q].z, v[q].w);
    }
    __syncthreads();

    #pragma unroll
    for (int t = 0; t < 4; t++){
        int cb = t & 1, nb = (t + 1) & 1;
        int k0n = (t + 1) * 64;
        float4 vn[4];
        if (t < 3){
            #pragma unroll
            for (int q = 0; q < 4; q++){
                int gr = row0 + rr[q];
                vn[q] = make_float4(0.f,0.f,0.f,0.f);
                if (gr < N) vn[q] = __ldg((const float4*)(x_e + (size_t)gr*EH + k0n) + (tid + 256*q & 15));
            }
        }
        #pragma unroll
        for (int kk = 0; kk < 4; kk++){
            wmma::fragment<wmma::matrix_b,16,16,16,__half,wmma::col_major> b;
            wmma::load_matrix_sync(b, Bfrag + (size_t)(warp*16 + t*4 + kk)*256, 16);
            #pragma unroll
            for (int rt = 0; rt < 4; rt++){
                wmma::fragment<wmma::matrix_a,16,16,16,__half,wmma::row_major> a;
                wmma::load_matrix_sync(a, &Asm[cb][(rt*4 + kk)*FSTR], FLD);
                wmma::mma_sync(acc[rt], a, b, acc[rt]);
            }
        }
        if (t < 3){
            #pragma unroll
            for (int q = 0; q < 4; q++){
                __half* base = &Asm[nb][(rtq[q]*4 + kkq[q])*FSTR + (rr[q] & 15)*FLD + kinq[q]];
                ((__half2*)base)[0] = __floats2half2_rn(vn[q].x, vn[q].y);
                ((__half2*)base)[1] = __floats2half2_rn(vn[q].z, vn[q].w);
            }
            __syncthreads();
        }
    }
    #pragma unroll
    for (int chunk = 0; chunk < 2; chunk++){
        __syncthreads();
        #pragma unroll
        for (int rtl = 0; rtl < 2; rtl++)
            wmma::store_matrix_sync(&Csm[rtl*16*RH + warp*16], acc[chunk*2 + rtl],
                                    RH, wmma::mem_row_major);
        __syncthreads();
        for (int i = tid; i < 32*64; i += 256){
            int r = i >> 6, c2 = i & 63;
            int gr = row0 + chunk*32 + r;
            if (gr < N)
                ((__half2*)(dstg + (size_t)gr*RH))[c2] =
                    __floats2half2_rn(Csm[r*RH + 2*c2], Csm[r*RH + 2*c2 + 1]);
        }
    }
}

// ---------------- kernel B: per-node scores (fp32 exact) ----------------
__global__ void kB(const float* __restrict__ x_e, int N){
    __shared__ float sU[8*EH];
    for (int i = threadIdx.x; i < 8*EH; i += blockDim.x) sU[i] = g_U[i];
    __syncthreads();
    int warp = threadIdx.x >> 5, lane = threadIdx.x & 31;
    int n = blockIdx.x*8 + warp;
    if (n >= N) return;
    const float4* row = (const float4*)(x_e + (size_t)n*EH);
    float4 v0 = __ldg(&row[lane]);
    float4 v1 = __ldg(&row[lane+32]);
    float p[8];
    #pragma unroll
    for (int j = 0; j < 8; j++){
        const float* U = &sU[j*EH];
        float s;
        s  = v0.x*U[lane*4+0] + v0.y*U[lane*4+1] + v0.z*U[lane*4+2] + v0.w*U[lane*4+3];
        s += v1.x*U[128+lane*4+0] + v1.y*U[128+lane*4+1]
           + v1.z*U[128+lane*4+2] + v1.w*U[128+lane*4+3];
        p[j] = s;
    }
    #pragma unroll
    for (int j = 0; j < 8; j++){
        #pragma unroll
        for (int o = 16; o > 0; o >>= 1) p[j] += __shfl_xor_sync(0xffffffffu, p[j], o);
    }
    if (lane == 0){
        g_Ssrc[n] = make_float4(p[0], p[1], p[2], p[3]);
        g_Sdst[n] = make_float4(p[4], p[5], p[6], p[7]);
    }
}

// ---- kernel S: per-rel scan across blocks -> prefixes + totals; last block scans totals ----
__global__ void __launch_bounds__(896) kS(){
    __shared__ int wsum[32];
    __shared__ int last;
    int r = blockIdx.x;
    int t = threadIdx.x, lane = t & 31, warp = t >> 5;   // 28 warps
    int v = (t < NB) ? g_bcnt[t*RREL + r] : 0;
    int incl = v;
    #pragma unroll
    for (int o = 1; o < 32; o <<= 1){
        int x = __shfl_up_sync(0xffffffffu, incl, o);
        if (lane >= o) incl += x;
    }
    if (lane == 31) wsum[warp] = incl;
    __syncthreads();
    if (warp == 0){
        int w = (lane < 28) ? wsum[lane] : 0;
        int wi = w;
        #pragma unroll
        for (int o = 1; o < 32; o <<= 1){
            int x = __shfl_up_sync(0xffffffffu, wi, o);
            if (lane >= o) wi += x;
        }
        wsum[lane] = wi - w;   // exclusive warp prefix
    }
    __syncthreads();
    int pos = wsum[warp] + incl;
    if (t < NB)      g_boff[t*RREL + r] = pos - v;
    if (t == NB - 1) g_cnt[r] = pos;
    __threadfence();
    if (t == 0) last = (atomicAdd(&g_done, 1) == (int)gridDim.x - 1);
    __syncthreads();
    if (last){
        __threadfence();
        if (t < 32){
            int carry = 0;
            for (int base = 0; base < RREL; base += 32){
                int idx  = base + t;
                int orig = (idx < RREL) ? g_cnt[idx] : 0;
                int vv = orig;
                #pragma unroll
                for (int o = 1; o < 32; o <<= 1){
                    int x = __shfl_up_sync(0xffffffffu, vv, o);
                    if (t >= o) vv += x;
                }
                if (idx < RREL) g_start[idx] = carry + vv - orig;
                carry += __shfl_sync(0xffffffffu, vv, 31);
            }
            if (t == 0){ g_start[RREL] = carry; g_done = 0; }  // reset for next replay
        }
    }
}

// ---------- kernel E: quad-batched exp + counting-sort scatter (NO sum atomics) ----------
__global__ void __launch_bounds__(256) kE(const int* __restrict__ ei,
                                          const int* __restrict__ rel, int E){
    __shared__ int scur[RREL];
    int b = blockIdx.x;
    for (int i = threadIdx.x; i < RREL; i += blockDim.x)
        scur[i] = g_start[i] + g_boff[b*RREL + i];
    __syncthreads();
    int e0 = b*ECHUNK, e1 = min(E, e0 + ECHUNK);
    int eb = e0 + threadIdx.x*4;
    if (eb < e1){
        int nv = min(4, e1 - eb);
        int s[4], d[4], rr[4];
        if (nv == 4){
            int4 vs = *(const int4*)&ei[eb];
            int4 vd = *(const int4*)&ei[E + eb];
            int4 vr = *(const int4*)&rel[eb];
            s[0]=vs.x; s[1]=vs.y; s[2]=vs.z; s[3]=vs.w;
            d[0]=vd.x; d[1]=vd.y; d[2]=vd.z; d[3]=vd.w;
            rr[0]=vr.x; rr[1]=vr.y; rr[2]=vr.z; rr[3]=vr.w;
        } else {
            for (int i = 0; i < nv; i++){
                s[i]  = ei[eb+i];
                d[i]  = ei[E+eb+i];
                rr[i] = rel[eb+i];
            }
        }
        float4 fs[4], fd[4];
        #pragma unroll
        for (int i = 0; i < 4; i++) if (i < nv){
            fs[i] = __ldg(&g_Ssrc[s[i]]);
            fd[i] = __ldg(&g_Sdst[d[i]]);
        }
        #pragma unroll
        for (int i = 0; i < 4; i++) if (i < nv){
            int r = rr[i];
            // scores ~ N(0,2): exp without max-shift is safe in fp32
            float x0 = __expf(lrelu(fs[i].x + fd[i].x));
            float x1 = __expf(lrelu(fs[i].y + fd[i].y));
            float x2 = __expf(lrelu(fs[i].z + fd[i].z));
            float x3 = __expf(lrelu(fs[i].w + fd[i].w));
            int pos = atomicAdd(&scur[r], 1);
            g_sM[pos] = make_float4(__int_as_float(s[i]), __int_as_float(d[i]),
                                    h2_as_f(__floats2half2_rn(x0, x1)),
                                    h2_as_f(__floats2half2_rn(x2, x3)));
        }
    }
}

// ---------- kernel Sum: per-rel exp sums from sorted meta (atomic-free, coalesced) ----------
__global__ void __launch_bounds__(256) kSum(){
    __shared__ float red[8][4];
    int r = blockIdx.x;
    int beg = g_start[r], end = g_start[r+1];
    float s0=0.f, s1=0.f, s2=0.f, s3=0.f;
    for (int i = beg + threadIdx.x; i < end; i += 256){
        float4 m = __ldg(&g_sM[i]);
        float2 e01 = __half22float2(f_as_h2(m.z));
        float2 e23 = __half22float2(f_as_h2(m.w));
        s0 += e01.x; s1 += e01.y; s2 += e23.x; s3 += e23.y;
    }
    #pragma unroll
    for (int o = 16; o > 0; o >>= 1){
        s0 += __shfl_xor_sync(0xffffffffu, s0, o);
        s1 += __shfl_xor_sync(0xffffffffu, s1, o);
        s2 += __shfl_xor_sync(0xffffffffu, s2, o);
        s3 += __shfl_xor_sync(0xffffffffu, s3, o);
    }
    int warp = threadIdx.x >> 5, lane = threadIdx.x & 31;
    if (lane == 0){ red[warp][0]=s0; red[warp][1]=s1; red[warp][2]=s2; red[warp][3]=s3; }
    __syncthreads();
    if (threadIdx.x < 4){
        float t = 0.f;
        #pragma unroll
        for (int w = 0; w < 8; w++) t += red[w][threadIdx.x];
        g_sum[4*r + threadIdx.x] = t;
    }
}

// ---------- kernel F: warp-per-edge, 8B/lane loads, depth-2 pipeline ----------
__global__ void __launch_bounds__(256) kF(float* __restrict__ out){
    __shared__ float4 redS[8][32];
    __shared__ float4 redD[8][32];
    int r    = blockIdx.x / SPLIT;
    int part = blockIdx.x % SPLIT;
    int beg = g_start[r], end = g_start[r+1], n = end - beg;
    int p0 = beg + (int)(((long long)n *  part     ) / SPLIT);
    int p1 = beg + (int)(((long long)n * (part + 1)) / SPLIT);
    float inv0 = 1.f/(g_sum[4*r+0] + 1e-16f);
    float inv1 = 1.f/(g_sum[4*r+1] + 1e-16f);
    float inv2 = 1.f/(g_sum[4*r+2] + 1e-16f);
    float inv3 = 1.f/(g_sum[4*r+3] + 1e-16f);
    int warp = threadIdx.x >> 5, lane = threadIdx.x & 31;

    float4 aS = make_float4(0.f,0.f,0.f,0.f);
    float4 aD = make_float4(0.f,0.f,0.f,0.f);

    int i = p0 + warp;
    float4 m0 = make_float4(0.f,0.f,0.f,0.f);
    uint2 hs0 = make_uint2(0u,0u), ht0 = make_uint2(0u,0u);
    if (i < p1){
        m0 = __ldg(&g_sM[i]);
        int s = __float_as_int(m0.x), d = __float_as_int(m0.y);
        hs0 = __ldg((const uint2*)(g_xrh + (size_t)s*RH) + lane);
        ht0 = __ldg((const uint2*)(g_xrt + (size_t)d*RH) + lane);
    }
    while (i < p1){
        int j = i + 8;
        float4 m1 = make_float4(0.f,0.f,0.f,0.f);
        uint2 hs1 = make_uint2(0u,0u), ht1 = make_uint2(0u,0u);
        if (j < p1){
            m1 = __ldg(&g_sM[j]);
            int s = __float_as_int(m1.x), d = __float_as_int(m1.y);
            hs1 = __ldg((const uint2*)(g_xrh + (size_t)s*RH) + lane);
            ht1 = __ldg((const uint2*)(g_xrt + (size_t)d*RH) + lane);
        }
        {
            float2 e01 = __half22float2(f_as_h2(m0.z));
            float2 e23 = __half22float2(f_as_h2(m0.w));
            float w1 = e01.x*inv0 + e01.y*inv1;
            float w2 = e23.x*inv2 + e23.y*inv3;
            float2 f;
            f = __half22float2(*reinterpret_cast<__half2*>(&hs0.x));
            aS.x = fmaf(w1, f.x, aS.x); aS.y = fmaf(w1, f.y, aS.y);
            f = __half22float2(*reinterpret_cast<__half2*>(&hs0.y));
            aS.z = fmaf(w1, f.x, aS.z); aS.w = fmaf(w1, f.y, aS.w);
            f = __half22float2(*reinterpret_cast<__half2*>(&ht0.x));
            aD.x = fmaf(w2, f.x, aD.x); aD.y = fmaf(w2, f.y, aD.y);
            f = __half22float2(*reinterpret_cast<__half2*>(&ht0.y));
            aD.z = fmaf(w2, f.x, aD.z); aD.w = fmaf(w2, f.y, aD.w);
        }
        m0 = m1; hs0 = hs1; ht0 = ht1; i = j;
    }

    redS[warp][lane] = aS;
    redD[warp][lane] = aD;
    __syncthreads();

    int t = threadIdx.x;
    if (t < 32){
        float4 s = make_float4(0.f,0.f,0.f,0.f);
        float4 dd = make_float4(0.f,0.f,0.f,0.f);
        #pragma unroll
        for (int w = 0; w < 8; w++){
            float4 vs = redS[w][t], vd = redD[w][t];
            s.x += vs.x; s.y += vs.y; s.z += vs.z; s.w += vs.w;
            dd.x += vd.x; dd.y += vd.y; dd.z += vd.z; dd.w += vd.w;
        }
        float* o = &out[r*RH + 4*t];
        atomicAdd(o+0, 0.25f*(s.x + dd.x));
        atomicAdd(o+1, 0.25f*(s.y + dd.y));
        atomicAdd(o+2, 0.25f*(s.z + dd.z));
        atomicAdd(o+3, 0.25f*(s.w + dd.w));
    }
}

// ---------------- streams/events (host-side objects, created at load time) ----------------
struct HXStreams {
    cudaStream_t sB, sC;
    cudaEvent_t  evRoot, evP, evB, evC;
    HXStreams(){
        cudaStreamCreateWithFlags(&sB, cudaStreamNonBlocking);
        cudaStreamCreateWithFlags(&sC, cudaStreamNonBlocking);
        cudaEventCreateWithFlags(&evRoot, cudaEventDisableTiming);
        cudaEventCreateWithFlags(&evP,    cudaEventDisableTiming);
        cudaEventCreateWithFlags(&evB,    cudaEventDisableTiming);
        cudaEventCreateWithFlags(&evC,    cudaEventDisableTiming);
    }
};
static HXStreams hx;

// ---------------- launcher: fork at the top, 3 chains, R12-style tail ----------------
extern "C" void kernel_launch(void* const* d_in, const int* in_sizes, int n_in,
                              void* d_out, int out_size){
    const float* x_e = (const float*)d_in[0];
    const int*   ei  = (const int*)  d_in[1];
    const int*   rel = (const int*)  d_in[2];
    const float* w_h = (const float*)d_in[3];
    const float* w_t = (const float*)d_in[4];
    const float* a_h = (const float*)d_in[5];
    const float* a_t = (const float*)d_in[6];
    float* out = (float*)d_out;

    int N = in_sizes[0] / EH;
    int E = in_sizes[2];

    // fork immediately
    cudaEventRecord(hx.evRoot, 0);
    cudaStreamWaitEvent(hx.sB, hx.evRoot, 0);
    cudaStreamWaitEvent(hx.sC, hx.evRoot, 0);

    // chain 2 (stream B): fused prep (U vectors + fp16 weights + zero out) -> kG
    kP<<<136, 256, 0, hx.sB>>>(w_h, w_t, a_h, a_t, out);
    cudaEventRecord(hx.evP, hx.sB);
    dim3 ggrid((N + GROWS - 1)/GROWS, 2);
    kG<<<ggrid, 256, 0, hx.sB>>>(x_e, N);
    cudaEventRecord(hx.evB, hx.sB);

    // chain 1 (main): scores (needs U from kP)
    cudaStreamWaitEvent(0, hx.evP, 0);
    kB<<<(N + 7)/8, 256>>>(x_e, N);

    // chain 3 (stream C): histogram -> prefix structure
    kH<<<NB, 256, 0, hx.sC>>>(rel, E);
    kS<<<RREL, 896, 0, hx.sC>>>();
    cudaEventRecord(hx.evC, hx.sC);

    // join: kE needs chains 1+3; kSum follows on the sorted meta
    cudaStreamWaitEvent(0, hx.evC, 0);
    kE<<<NB, 256>>>(ei, rel, E);
    kSum<<<RREL, 256>>>();

    // join: kF needs chain 2
    cudaStreamWaitEvent(0, hx.evB, 0);
    kF<<<RREL*SPLIT, 256>>>(out);
}